// round 9
// baseline (speedup 1.0000x reference)
#include <cuda_runtime.h>
#include <cuda_bf16.h>
#include <math.h>

// Problem constants
#define FD      128
#define K       15
#define FS      160
#define OV      40
#define NF      500
#define BATCH   32
#define NTOT    (NF * FS)          // 80000 samples per batch row
#define NFR     (BATCH * NF)       // 16000 frames total

// C = ln(10)/20 ; LOG_GAIN_LIMIT = 10*C ; GAIN_A = 6*C ; GAIN_B = 0
#define LOG_GAIN_LIMIT 1.1512925464970229f
#define GAIN_A         0.6907755278982137f
#define PI_F           3.14159265358979323846f

// Per-frame coefficients: [0..14] = taps * gain / ||k||  (folded), [15] = ggain
__device__ float g_coef[NFR * 16];

// ---------------------------------------------------------------------------
// Kernel A: one warp per frame. 8 lanes per dot row, 4 rows per iteration,
// 5 iterations cover the 17 rows (15 comb taps + fg + gg projections).
// Reduction is 3 shuffle levels within 8 lanes (vs 5 levels x 17 rows before).
// ---------------------------------------------------------------------------
__global__ __launch_bounds__(256)
void dots_kernel(const float* __restrict__ features,
                 const float* __restrict__ ck_w, const float* __restrict__ ck_b,
                 const float* __restrict__ fg_w, const float* __restrict__ fg_b,
                 const float* __restrict__ gg_w, const float* __restrict__ gg_b)
{
    __shared__ float s_dot[8][20];
    const int lane = threadIdx.x & 31;
    const int warp = threadIdx.x >> 5;
    const int fr   = blockIdx.x * 8 + warp;     // grid = NFR/8 exactly
    const int seg  = lane & 7;                  // 16-feature segment owned by lane
    const int rgrp = lane >> 3;                 // row within the 4-row group

    // this lane's 16 features, as 4 float4
    const float4* fp = (const float4*)(features + (size_t)fr * FD) + seg * 4;
    float4 f0 = __ldg(fp + 0), f1 = __ldg(fp + 1),
           f2 = __ldg(fp + 2), f3 = __ldg(fp + 3);

    #pragma unroll
    for (int it = 0; it < 5; it++) {
        const int row = it * 4 + rgrp;
        const bool valid = (row < 17);
        float s = 0.f;
        if (valid) {
            const float* w = (row < 15) ? (ck_w + row * FD)
                                        : (row == 15 ? fg_w : gg_w);
            const float4* wp = (const float4*)w + seg * 4;
            float4 w0 = __ldg(wp + 0), w1 = __ldg(wp + 1),
                   w2 = __ldg(wp + 2), w3 = __ldg(wp + 3);
            s  = f0.x*w0.x + f0.y*w0.y + f0.z*w0.z + f0.w*w0.w;
            s += f1.x*w1.x + f1.y*w1.y + f1.z*w1.z + f1.w*w1.w;
            s += f2.x*w2.x + f2.y*w2.y + f2.z*w2.z + f2.w*w2.w;
            s += f3.x*w3.x + f3.y*w3.y + f3.z*w3.z + f3.w*w3.w;
        }
        s += __shfl_xor_sync(0xffffffffu, s, 1);
        s += __shfl_xor_sync(0xffffffffu, s, 2);
        s += __shfl_xor_sync(0xffffffffu, s, 4);
        if (valid && seg == 0) s_dot[warp][row] = s;
    }
    __syncwarp();

    // epilogue: lane r holds dot r (+bias) for r < 17
    float d = 0.f;
    if (lane < 17) {
        const float bias = (lane < 15) ? __ldg(ck_b + lane)
                         : (lane == 15) ? __ldg(fg_b) : __ldg(gg_b);
        d = s_dot[warp][lane] + bias;
    }

    float sq = (lane < 15) ? d * d : 0.f;
    #pragma unroll
    for (int off = 16; off; off >>= 1)
        sq += __shfl_xor_sync(0xffffffffu, sq, off);

    const float fgd = __shfl_sync(0xffffffffu, d, 15);
    const float ggd = __shfl_sync(0xffffffffu, d, 16);

    const float gain = __expf(LOG_GAIN_LIMIT - fmaxf(fgd, 0.f));
    const float gs   = gain / (1e-6f + sqrtf(sq));   // fold normalization into gain

    if (lane < 15)       g_coef[fr * 16 + lane] = d * gs;
    else if (lane == 15) g_coef[fr * 16 + 15]   = __expf(GAIN_A * tanhf(ggd));
}

// ---------------------------------------------------------------------------
// Kernel B: one warp per frame, warp-synchronous. Shared per warp (420 floats):
//   [  0..174)  xc : lag-gathered window, current frame
//   [174..228)  xp : lag-gathered window, prev-frame tail
//   [228..388)  pt : pass-through x[f*FS .. +160)   (float4-staged)
//   [388..404)  coefs current frame (15 taps + gg)
//   [404..420)  coefs previous frame
// Lane computes 5 outputs from a 19-float register window; lanes 0..7 also
// recompute the prev frame's 40-sample tail and apply the crossfade.
// ---------------------------------------------------------------------------
__global__ __launch_bounds__(128)
void fir_kernel(const float* __restrict__ x,
                const int*   __restrict__ lags,
                float*       __restrict__ out)
{
    __shared__ __align__(16) float sh[4][420];
    const int lane = threadIdx.x & 31;
    const int warp = threadIdx.x >> 5;
    const int fr   = blockIdx.x * 4 + warp;     // grid = NFR/4 exactly
    const int b    = fr / NF;
    const int f    = fr % NF;

    const float* xb = x + (size_t)b * NTOT;
    float* s = sh[warp];
    const int base = f * FS - 7;                // f*FS - PAD_L
    const int lag  = __ldg(lags + fr);

    // ---- stage xc (174) ----------------------------------------------------
    // left pad only possible for f<2 (lag<256, base>=313 for f>=2);
    // right pad only possible for f=499 (base+173 <= 79846 for f<=498).
    if (f >= 2 && f <= 498) {
        const float* src = xb + (base - lag);
        #pragma unroll
        for (int t = lane; t < 174; t += 32) s[t] = __ldg(src + t);
    } else {
        #pragma unroll
        for (int t = lane; t < 174; t += 32) {
            const int idx = base - lag + t;
            s[t] = (idx >= 0 && idx < NTOT) ? __ldg(xb + idx) : 0.f;
        }
    }

    // ---- stage xp (54), only needed for f>0 --------------------------------
    if (f >= 2) {
        const int lagp = __ldg(lags + fr - 1);
        const float* src = xb + (base - lagp);
        #pragma unroll
        for (int t = lane; t < 54; t += 32) s[174 + t] = __ldg(src + t);
    } else if (f == 1) {
        const int lagp = __ldg(lags + fr - 1);
        #pragma unroll
        for (int t = lane; t < 54; t += 32) {
            const int idx = base - lagp + t;
            s[174 + t] = (idx >= 0) ? __ldg(xb + idx) : 0.f;
        }
    }

    // ---- stage pt (160) as float4 (f*FS is 16B aligned) --------------------
    {
        const float4* ptg = (const float4*)(xb + f * FS);
        float4* pts = (float4*)(s + 228);
        pts[lane] = __ldg(ptg + lane);
        if (lane < 8) pts[32 + lane] = __ldg(ptg + 32 + lane);
    }

    // ---- stage coefficients ------------------------------------------------
    if (lane < 16)       s[388 + lane]        = g_coef[fr * 16 + lane];
    else if (f > 0)      s[404 + (lane - 16)] = g_coef[(fr - 1) * 16 + (lane - 16)];
    __syncwarp();

    float tap[15];
    #pragma unroll
    for (int k = 0; k < 15; k++) tap[k] = s[388 + k];
    const float gg = s[403];

    float xv[19];
    #pragma unroll
    for (int j = 0; j < 19; j++) xv[j] = s[5 * lane + j];

    float res[5];
    #pragma unroll
    for (int i = 0; i < 5; i++) {
        float conv = 0.f;
        #pragma unroll
        for (int k = 0; k < 15; k++)
            conv = fmaf(xv[i + k], tap[k], conv);
        res[i] = gg * (conv + s[228 + 5 * lane + i]);
    }

    // head region o<40: crossfade with previous frame's recomputed tail
    if (lane < 8) {
        float tailv[5] = {0.f, 0.f, 0.f, 0.f, 0.f};
        if (f > 0) {
            float tp[15];
            #pragma unroll
            for (int k = 0; k < 15; k++) tp[k] = s[404 + k];
            const float ggp = s[419];
            float xpw[19];
            #pragma unroll
            for (int j = 0; j < 19; j++) xpw[j] = s[174 + 5 * lane + j];
            #pragma unroll
            for (int i = 0; i < 5; i++) {
                float cp = 0.f;
                #pragma unroll
                for (int k = 0; k < 15; k++)
                    cp = fmaf(xpw[i + k], tp[k], cp);
                // prev frame's pass-through at l=FS+j equals x[f*FS + j] = pt[j]
                tailv[i] = ggp * (cp + s[228 + 5 * lane + i]);
            }
        }
        #pragma unroll
        for (int i = 0; i < 5; i++) {
            const int j = 5 * lane + i;
            const float w2 = 0.5f + 0.5f * __cosf((j + 0.5f) * (PI_F / OV));
            res[i] = res[i] * (1.f - w2) + tailv[i] * w2;   // win1 = 1 - win2
        }
    }

    // bounce through shared (reuse xc region) for coalesced stores
    __syncwarp();
    #pragma unroll
    for (int i = 0; i < 5; i++) s[5 * lane + i] = res[i];
    __syncwarp();

    float* op = out + (size_t)b * NTOT + f * FS;
    #pragma unroll
    for (int i = 0; i < 5; i++)
        op[lane + 32 * i] = s[lane + 32 * i];
}

extern "C" void kernel_launch(void* const* d_in, const int* in_sizes, int n_in,
                              void* d_out, int out_size)
{
    const float* x        = (const float*)d_in[0];
    const float* features = (const float*)d_in[1];
    const int*   lags     = (const int*)  d_in[2];
    const float* ck_w     = (const float*)d_in[3];
    const float* ck_b     = (const float*)d_in[4];
    const float* fg_w     = (const float*)d_in[5];
    const float* fg_b     = (const float*)d_in[6];
    const float* gg_w     = (const float*)d_in[7];
    const float* gg_b     = (const float*)d_in[8];

    dots_kernel<<<NFR / 8, 256>>>(features, ck_w, ck_b, fg_w, fg_b, gg_w, gg_b);
    fir_kernel<<<NFR / 4, 128>>>(x, lags, (float*)d_out);
}

// round 10
// speedup vs baseline: 2.0467x; 2.0467x over previous
#include <cuda_runtime.h>
#include <cuda_bf16.h>
#include <math.h>

// Problem constants
#define FD      128
#define K       15
#define FS      160
#define OV      40
#define NF      500
#define BATCH   32
#define NTOT    (NF * FS)          // 80000 samples per batch row
#define NFR     (BATCH * NF)       // 16000 frames total

// C = ln(10)/20 ; LOG_GAIN_LIMIT = 10*C ; GAIN_A = 6*C ; GAIN_B = 0
#define LOG_GAIN_LIMIT 1.1512925464970229f
#define GAIN_A         0.6907755278982137f
#define PI_F           3.14159265358979323846f

// Per-frame coefficients: [0..14] = taps * gain / ||k||  (folded), [15] = ggain
__device__ float g_coef[NFR * 16];

// ---------------------------------------------------------------------------
// Kernel A: one warp per frame. Half-warp per row, 2 rows per iteration,
// 9 iterations cover 17 rows (15 comb taps + fg + gg projections).
// Each weight LDG touches exactly 2 row pointers (4 cache lines per instr,
// same as a full-row load) while shuffle count drops 85 -> 36 per lane.
// ---------------------------------------------------------------------------
__global__ __launch_bounds__(256)
void dots_kernel(const float* __restrict__ features,
                 const float* __restrict__ ck_w, const float* __restrict__ ck_b,
                 const float* __restrict__ fg_w, const float* __restrict__ fg_b,
                 const float* __restrict__ gg_w, const float* __restrict__ gg_b)
{
    __shared__ float s_dot[8][20];
    const int lane  = threadIdx.x & 31;
    const int warp  = threadIdx.x >> 5;
    const int fr    = blockIdx.x * 8 + warp;    // grid = NFR/8 exactly
    const int hlane = lane & 15;                // position within half-warp
    const int half  = lane >> 4;                // 0: even rows, 1: odd rows

    // this lane's 8 features (2 float4)
    const float4* fp = (const float4*)(features + (size_t)fr * FD) + hlane * 2;
    const float4 fa = __ldg(fp + 0);
    const float4 fb = __ldg(fp + 1);

    #pragma unroll
    for (int it = 0; it < 9; it++) {
        const int row = it * 2 + half;          // half 0: 0,2,..,16 ; half 1: 1,3,..,17
        float s = 0.f;
        if (row < 17) {
            const float* w = (row < 15) ? (ck_w + row * FD)
                                        : (row == 15 ? fg_w : gg_w);
            const float4* wp = (const float4*)w + hlane * 2;
            const float4 wa = __ldg(wp + 0);
            const float4 wb = __ldg(wp + 1);
            s  = fa.x*wa.x + fa.y*wa.y + fa.z*wa.z + fa.w*wa.w;
            s += fb.x*wb.x + fb.y*wb.y + fb.z*wb.z + fb.w*wb.w;
        }
        // reduce within each half-warp (xor offsets stay inside the half)
        s += __shfl_xor_sync(0xffffffffu, s, 1);
        s += __shfl_xor_sync(0xffffffffu, s, 2);
        s += __shfl_xor_sync(0xffffffffu, s, 4);
        s += __shfl_xor_sync(0xffffffffu, s, 8);
        if (row < 17 && hlane == 0) s_dot[warp][row] = s;
    }
    __syncwarp();

    // epilogue: lane r holds dot r (+bias) for r < 17
    float d = 0.f;
    if (lane < 17) {
        const float bias = (lane < 15) ? __ldg(ck_b + lane)
                         : (lane == 15) ? __ldg(fg_b) : __ldg(gg_b);
        d = s_dot[warp][lane] + bias;
    }

    float sq = (lane < 15) ? d * d : 0.f;
    #pragma unroll
    for (int off = 16; off; off >>= 1)
        sq += __shfl_xor_sync(0xffffffffu, sq, off);

    const float fgd = __shfl_sync(0xffffffffu, d, 15);
    const float ggd = __shfl_sync(0xffffffffu, d, 16);

    const float gain = __expf(LOG_GAIN_LIMIT - fmaxf(fgd, 0.f));
    const float gs   = gain / (1e-6f + sqrtf(sq));   // fold normalization into gain

    if (lane < 15)       g_coef[fr * 16 + lane] = d * gs;
    else if (lane == 15) g_coef[fr * 16 + 15]   = __expf(GAIN_A * tanhf(ggd));
}

// ---------------------------------------------------------------------------
// Kernel B: one warp per frame, warp-synchronous, 256-thread blocks (R8 shape).
// Shared per warp (420 floats):
//   [  0..174)  xc : lag-gathered window, current frame
//   [174..228)  xp : lag-gathered window, prev-frame tail
//   [228..388)  pt : pass-through x[f*FS .. +160)   (float4-staged)
//   [388..404)  coefs current frame (15 taps + gg)
//   [404..420)  coefs previous frame
// Lane computes 5 outputs from a 19-float register window; lanes 0..7 also
// recompute the prev frame's 40-sample tail and apply the crossfade.
// ---------------------------------------------------------------------------
__global__ __launch_bounds__(256)
void fir_kernel(const float* __restrict__ x,
                const int*   __restrict__ lags,
                float*       __restrict__ out)
{
    __shared__ __align__(16) float sh[8][420];
    const int lane = threadIdx.x & 31;
    const int warp = threadIdx.x >> 5;
    const int fr   = blockIdx.x * 8 + warp;     // grid = NFR/8 exactly
    const int b    = fr / NF;
    const int f    = fr % NF;

    const float* xb = x + (size_t)b * NTOT;
    float* s = sh[warp];
    const int base = f * FS - 7;                // f*FS - PAD_L
    const int lag  = __ldg(lags + fr);

    // ---- stage xc (174) ----------------------------------------------------
    // left pad only possible for f<2 (lag<256; base>=313 for f>=2);
    // right pad only possible for f=499 (base+173 <= 79846 for f<=498).
    if (f >= 2 && f <= 498) {
        const float* src = xb + (base - lag);
        #pragma unroll
        for (int t = lane; t < 174; t += 32) s[t] = __ldg(src + t);
    } else {
        #pragma unroll
        for (int t = lane; t < 174; t += 32) {
            const int idx = base - lag + t;
            s[t] = (idx >= 0 && idx < NTOT) ? __ldg(xb + idx) : 0.f;
        }
    }

    // ---- stage xp (54), only needed for f>0 --------------------------------
    if (f >= 2) {
        const int lagp = __ldg(lags + fr - 1);
        const float* src = xb + (base - lagp);
        #pragma unroll
        for (int t = lane; t < 54; t += 32) s[174 + t] = __ldg(src + t);
    } else if (f == 1) {
        const int lagp = __ldg(lags + fr - 1);
        #pragma unroll
        for (int t = lane; t < 54; t += 32) {
            const int idx = base - lagp + t;
            s[174 + t] = (idx >= 0) ? __ldg(xb + idx) : 0.f;
        }
    }

    // ---- stage pt (160) as float4 (f*FS is 16B aligned) --------------------
    {
        const float4* ptg = (const float4*)(xb + f * FS);
        float4* pts = (float4*)(s + 228);
        pts[lane] = __ldg(ptg + lane);
        if (lane < 8) pts[32 + lane] = __ldg(ptg + 32 + lane);
    }

    // ---- stage coefficients ------------------------------------------------
    if (lane < 16)       s[388 + lane]        = g_coef[fr * 16 + lane];
    else if (f > 0)      s[404 + (lane - 16)] = g_coef[(fr - 1) * 16 + (lane - 16)];
    __syncwarp();

    float tap[15];
    #pragma unroll
    for (int k = 0; k < 15; k++) tap[k] = s[388 + k];
    const float gg = s[403];

    float xv[19];
    #pragma unroll
    for (int j = 0; j < 19; j++) xv[j] = s[5 * lane + j];

    float res[5];
    #pragma unroll
    for (int i = 0; i < 5; i++) {
        float conv = 0.f;
        #pragma unroll
        for (int k = 0; k < 15; k++)
            conv = fmaf(xv[i + k], tap[k], conv);
        res[i] = gg * (conv + s[228 + 5 * lane + i]);
    }

    // head region o<40: crossfade with previous frame's recomputed tail
    if (lane < 8) {
        float tailv[5] = {0.f, 0.f, 0.f, 0.f, 0.f};
        if (f > 0) {
            float tp[15];
            #pragma unroll
            for (int k = 0; k < 15; k++) tp[k] = s[404 + k];
            const float ggp = s[419];
            float xpw[19];
            #pragma unroll
            for (int j = 0; j < 19; j++) xpw[j] = s[174 + 5 * lane + j];
            #pragma unroll
            for (int i = 0; i < 5; i++) {
                float cp = 0.f;
                #pragma unroll
                for (int k = 0; k < 15; k++)
                    cp = fmaf(xpw[i + k], tp[k], cp);
                // prev frame's pass-through at l=FS+j equals x[f*FS + j] = pt[j]
                tailv[i] = ggp * (cp + s[228 + 5 * lane + i]);
            }
        }
        #pragma unroll
        for (int i = 0; i < 5; i++) {
            const int j = 5 * lane + i;
            const float w2 = 0.5f + 0.5f * __cosf((j + 0.5f) * (PI_F / OV));
            res[i] = res[i] * (1.f - w2) + tailv[i] * w2;   // win1 = 1 - win2
        }
    }

    // bounce through shared (reuse xc region) for coalesced stores
    __syncwarp();
    #pragma unroll
    for (int i = 0; i < 5; i++) s[5 * lane + i] = res[i];
    __syncwarp();

    float* op = out + (size_t)b * NTOT + f * FS;
    #pragma unroll
    for (int i = 0; i < 5; i++)
        op[lane + 32 * i] = s[lane + 32 * i];
}

extern "C" void kernel_launch(void* const* d_in, const int* in_sizes, int n_in,
                              void* d_out, int out_size)
{
    const float* x        = (const float*)d_in[0];
    const float* features = (const float*)d_in[1];
    const int*   lags     = (const int*)  d_in[2];
    const float* ck_w     = (const float*)d_in[3];
    const float* ck_b     = (const float*)d_in[4];
    const float* fg_w     = (const float*)d_in[5];
    const float* fg_b     = (const float*)d_in[6];
    const float* gg_w     = (const float*)d_in[7];
    const float* gg_b     = (const float*)d_in[8];

    dots_kernel<<<NFR / 8, 256>>>(features, ck_w, ck_b, fg_w, fg_b, gg_w, gg_b);
    fir_kernel<<<NFR / 8, 256>>>(x, lags, (float*)d_out);
}